// round 1
// baseline (speedup 1.0000x reference)
#include <cuda_runtime.h>
#include <math.h>

#define D_MODEL 1024
#define NUM_HEADS 16
#define D_K 64
#define BATCH 4
#define SEQ 2048
#define BH (BATCH * NUM_HEADS)          // 64
#define M_ROWS (BATCH * SEQ)            // 8192

// Scratch (device globals; no dynamic allocation allowed)
__device__ float g_q[(size_t)BH * SEQ * D_K];
__device__ float g_k[(size_t)BH * SEQ * D_K];
__device__ float g_v[(size_t)BH * SEQ * D_K];
__device__ float g_ctx[(size_t)M_ROWS * D_MODEL];
// Fallback attention buffer if the harness output only holds `out`
__device__ float g_attn_fb[(size_t)BH * SEQ * SEQ];

// ---------------------------------------------------------------------------
// Projection GEMM: Y = X @ W^T + b
//   X: (M, 1024) row-major, W: (1024, 1024) row-major (PyTorch Linear weight)
//   SPLIT_HEADS: store Y in (B, H, S, d_k) layout instead of (M, 1024)
// Tiling: 64x64 block tile, BK=32, 256 threads, 4x4 per thread.
// ---------------------------------------------------------------------------
template <bool SPLIT_HEADS>
__global__ void proj_kernel(const float* __restrict__ X,
                            const float* __restrict__ W,
                            const float* __restrict__ bias,
                            float* __restrict__ Y) {
    __shared__ float As[32][65];  // [k][m], padded
    __shared__ float Bs[32][65];  // [k][n], padded

    const int bm = blockIdx.y * 64;
    const int bn = blockIdx.x * 64;
    const int tid = threadIdx.x;
    const int ty = tid >> 4;  // 0..15 (m group)
    const int tx = tid & 15;  // 0..15 (n group)

    float acc[4][4];
#pragma unroll
    for (int i = 0; i < 4; i++)
#pragma unroll
        for (int j = 0; j < 4; j++) acc[i][j] = 0.f;

    for (int k0 = 0; k0 < D_MODEL; k0 += 32) {
#pragma unroll
        for (int l = 0; l < 8; l++) {
            int t = tid + l * 256;       // 0..2047
            int r = t >> 5;              // 0..63
            int c = t & 31;              // 0..31
            As[c][r] = X[(size_t)(bm + r) * D_MODEL + k0 + c];
            Bs[c][r] = W[(size_t)(bn + r) * D_MODEL + k0 + c];
        }
        __syncthreads();
#pragma unroll
        for (int kk = 0; kk < 32; kk++) {
            float a[4], b[4];
#pragma unroll
            for (int i = 0; i < 4; i++) a[i] = As[kk][ty * 4 + i];
#pragma unroll
            for (int j = 0; j < 4; j++) b[j] = Bs[kk][tx * 4 + j];
#pragma unroll
            for (int i = 0; i < 4; i++)
#pragma unroll
                for (int j = 0; j < 4; j++) acc[i][j] += a[i] * b[j];
        }
        __syncthreads();
    }

#pragma unroll
    for (int i = 0; i < 4; i++) {
        int m = bm + ty * 4 + i;
#pragma unroll
        for (int j = 0; j < 4; j++) {
            int n = bn + tx * 4 + j;
            float val = acc[i][j] + bias[n];
            if (SPLIT_HEADS) {
                int b_ = m / SEQ, s_ = m % SEQ;
                int h = n / D_K, d = n % D_K;
                Y[(((size_t)(b_ * NUM_HEADS + h) * SEQ) + s_) * D_K + d] = val;
            } else {
                Y[(size_t)m * D_MODEL + n] = val;
            }
        }
    }
}

// ---------------------------------------------------------------------------
// Scores: attn[bh, i, j] = scale * sum_d q[bh,i,d] * k[bh,j,d]
// 64x64 tile per block, d_k = 64 fully in smem.
// ---------------------------------------------------------------------------
__global__ void scores_kernel(float* __restrict__ attn) {
    __shared__ float Qs[64][65];  // [d][i]
    __shared__ float Ks[64][65];  // [d][j]

    const int bh = blockIdx.z;
    const int bi = blockIdx.y * 64;
    const int bj = blockIdx.x * 64;
    const float* q = g_q + (size_t)bh * SEQ * D_K;
    const float* k = g_k + (size_t)bh * SEQ * D_K;
    const int tid = threadIdx.x;
    const int ty = tid >> 4, tx = tid & 15;

#pragma unroll
    for (int l = 0; l < 16; l++) {
        int t = tid + l * 256;   // 0..4095
        int r = t >> 6;          // row 0..63
        int c = t & 63;          // d 0..63
        Qs[c][r] = q[(size_t)(bi + r) * D_K + c];
        Ks[c][r] = k[(size_t)(bj + r) * D_K + c];
    }
    __syncthreads();

    float acc[4][4];
#pragma unroll
    for (int i = 0; i < 4; i++)
#pragma unroll
        for (int j = 0; j < 4; j++) acc[i][j] = 0.f;

#pragma unroll 8
    for (int kk = 0; kk < 64; kk++) {
        float a[4], b[4];
#pragma unroll
        for (int i = 0; i < 4; i++) a[i] = Qs[kk][ty * 4 + i];
#pragma unroll
        for (int j = 0; j < 4; j++) b[j] = Ks[kk][tx * 4 + j];
#pragma unroll
        for (int i = 0; i < 4; i++)
#pragma unroll
            for (int j = 0; j < 4; j++) acc[i][j] += a[i] * b[j];
    }

    const float scale = 0.125f;  // 1/sqrt(64)
    float* out = attn + (size_t)bh * SEQ * SEQ;
#pragma unroll
    for (int i = 0; i < 4; i++) {
        int ii = bi + ty * 4 + i;
#pragma unroll
        for (int j = 0; j < 4; j++) {
            out[(size_t)ii * SEQ + bj + tx * 4 + j] = acc[i][j] * scale;
        }
    }
}

// ---------------------------------------------------------------------------
// Row softmax in place. One block (256 threads) per row of length 2048.
// ---------------------------------------------------------------------------
__global__ void softmax_kernel(float* __restrict__ attn) {
    const size_t row = blockIdx.x;
    float* p = attn + row * SEQ;
    const int tid = threadIdx.x;

    float v[8];
#pragma unroll
    for (int i = 0; i < 8; i++) v[i] = p[tid + i * 256];

    float m = v[0];
#pragma unroll
    for (int i = 1; i < 8; i++) m = fmaxf(m, v[i]);

    __shared__ float red[32];
    // warp reduce max
#pragma unroll
    for (int o = 16; o > 0; o >>= 1) m = fmaxf(m, __shfl_xor_sync(0xffffffffu, m, o));
    if ((tid & 31) == 0) red[tid >> 5] = m;
    __syncthreads();
    if (tid < 32) {
        float t = (tid < 8) ? red[tid] : -1e30f;
#pragma unroll
        for (int o = 4; o > 0; o >>= 1) t = fmaxf(t, __shfl_xor_sync(0xffffffffu, t, o));
        if (tid == 0) red[0] = t;
    }
    __syncthreads();
    m = red[0];

    float s = 0.f;
#pragma unroll
    for (int i = 0; i < 8; i++) {
        v[i] = __expf(v[i] - m);
        s += v[i];
    }
#pragma unroll
    for (int o = 16; o > 0; o >>= 1) s += __shfl_xor_sync(0xffffffffu, s, o);
    __syncthreads();
    if ((tid & 31) == 0) red[tid >> 5] = s;
    __syncthreads();
    if (tid < 32) {
        float t = (tid < 8) ? red[tid] : 0.f;
#pragma unroll
        for (int o = 4; o > 0; o >>= 1) t += __shfl_xor_sync(0xffffffffu, t, o);
        if (tid == 0) red[0] = t;
    }
    __syncthreads();
    float inv = 1.f / red[0];

#pragma unroll
    for (int i = 0; i < 8; i++) p[tid + i * 256] = v[i] * inv;
}

// ---------------------------------------------------------------------------
// ctx[b, s, h*64+d] = sum_j attn[bh, i, j] * v[bh, j, d]
// Block: 64 rows (i), full 64 cols (d). BK = 32, K = 2048.
// ---------------------------------------------------------------------------
__global__ void ctx_kernel(const float* __restrict__ attn) {
    __shared__ float As[64][33];  // [i][k], padded
    __shared__ float Bs[32][65];  // [k][d], padded

    const int bh = blockIdx.z;
    const int bi = blockIdx.x * 64;
    const float* a = attn + (size_t)bh * SEQ * SEQ;
    const float* v = g_v + (size_t)bh * SEQ * D_K;
    const int tid = threadIdx.x;
    const int ty = tid >> 4, tx = tid & 15;

    float acc[4][4];
#pragma unroll
    for (int i = 0; i < 4; i++)
#pragma unroll
        for (int j = 0; j < 4; j++) acc[i][j] = 0.f;

    for (int k0 = 0; k0 < SEQ; k0 += 32) {
#pragma unroll
        for (int l = 0; l < 8; l++) {
            int t = tid + l * 256;  // 0..2047
            int r = t >> 5;         // 0..63
            int c = t & 31;         // 0..31
            As[r][c] = a[(size_t)(bi + r) * SEQ + k0 + c];
            // v tile: rows j (k dim), cols d
            int jr = t >> 6;        // 0..31
            int dc = t & 63;        // 0..63
            Bs[jr][dc] = v[(size_t)(k0 + jr) * D_K + dc];
        }
        __syncthreads();
#pragma unroll
        for (int kk = 0; kk < 32; kk++) {
            float aa[4], bb[4];
#pragma unroll
            for (int i = 0; i < 4; i++) aa[i] = As[ty * 4 + i][kk];
#pragma unroll
            for (int j = 0; j < 4; j++) bb[j] = Bs[kk][tx * 4 + j];
#pragma unroll
            for (int i = 0; i < 4; i++)
#pragma unroll
                for (int j = 0; j < 4; j++) acc[i][j] += aa[i] * bb[j];
        }
        __syncthreads();
    }

    const int b_ = bh / NUM_HEADS;
    const int h = bh % NUM_HEADS;
#pragma unroll
    for (int i = 0; i < 4; i++) {
        int s_ = bi + ty * 4 + i;
#pragma unroll
        for (int j = 0; j < 4; j++) {
            int d = tx * 4 + j;
            g_ctx[((size_t)b_ * SEQ + s_) * D_MODEL + h * D_K + d] = acc[i][j];
        }
    }
}

extern "C" void kernel_launch(void* const* d_in, const int* in_sizes, int n_in,
                              void* d_out, int out_size) {
    const float* Q  = (const float*)d_in[0];
    const float* K  = (const float*)d_in[1];
    const float* V  = (const float*)d_in[2];
    const float* Wq = (const float*)d_in[3];
    const float* bq = (const float*)d_in[4];
    const float* Wk = (const float*)d_in[5];
    const float* bk = (const float*)d_in[6];
    const float* Wv = (const float*)d_in[7];
    const float* bv = (const float*)d_in[8];
    const float* Wo = (const float*)d_in[9];
    const float* bo = (const float*)d_in[10];

    float* out = (float*)d_out;

    const size_t OUT_ELEMS = (size_t)M_ROWS * D_MODEL;             // 8,388,608
    const size_t ATTN_ELEMS = (size_t)BH * SEQ * SEQ;              // 268,435,456

    float* attn;
    if ((size_t)out_size >= OUT_ELEMS + ATTN_ELEMS) {
        attn = out + OUT_ELEMS;
    } else {
        void* p = nullptr;
        cudaGetSymbolAddress(&p, g_attn_fb);
        attn = (float*)p;
    }

    float *qp, *kp, *vp, *cp;
    { void* t; cudaGetSymbolAddress(&t, g_q);   qp = (float*)t; }
    { void* t; cudaGetSymbolAddress(&t, g_k);   kp = (float*)t; }
    { void* t; cudaGetSymbolAddress(&t, g_v);   vp = (float*)t; }
    { void* t; cudaGetSymbolAddress(&t, g_ctx); cp = (float*)t; }

    dim3 projGrid(D_MODEL / 64, M_ROWS / 64);   // (16, 128)
    proj_kernel<true><<<projGrid, 256>>>(Q, Wq, bq, qp);
    proj_kernel<true><<<projGrid, 256>>>(K, Wk, bk, kp);
    proj_kernel<true><<<projGrid, 256>>>(V, Wv, bv, vp);

    dim3 scoresGrid(SEQ / 64, SEQ / 64, BH);    // (32, 32, 64)
    scores_kernel<<<scoresGrid, 256>>>(attn);

    softmax_kernel<<<(unsigned)((size_t)BH * SEQ), 256>>>(attn);

    dim3 ctxGrid(SEQ / 64, 1, BH);              // (32, 1, 64)
    ctx_kernel<<<ctxGrid, 256>>>(attn);

    proj_kernel<false><<<projGrid, 256>>>(cp, Wo, bo, out);
}

// round 3
// speedup vs baseline: 2.2281x; 2.2281x over previous
#include <cuda_runtime.h>
#include <cstdint>

#define D_MODEL 1024
#define NUM_HEADS 16
#define D_K 64
#define BATCH 4
#define SEQ 2048
#define BH (BATCH * NUM_HEADS)          // 64
#define M_ROWS (BATCH * SEQ)            // 8192

// Scratch (device globals; no dynamic allocation allowed)
__device__ float g_q[(size_t)BH * SEQ * D_K];
__device__ float g_k[(size_t)BH * SEQ * D_K];
__device__ float g_vt[(size_t)BH * D_K * SEQ];   // V transposed: [bh][d][s]
__device__ float g_ctx[(size_t)M_ROWS * D_MODEL];
__device__ float g_attn_fb[(size_t)BH * SEQ * SEQ];

// Round fp32 -> tf32 (round-to-nearest; HMMA then truncates losslessly)
__device__ __forceinline__ uint32_t rn_tf32(float x) {
    return (__float_as_uint(x) + 0x1000u) & 0xFFFFE000u;
}

// Warp-level tf32 MMA (baseline PTX, compiles for sm_103 family)
__device__ __forceinline__ void mma_tf32(float* d, const uint32_t* a, const uint32_t* b) {
    asm volatile(
        "mma.sync.aligned.m16n8k8.row.col.f32.tf32.tf32.f32 "
        "{%0,%1,%2,%3}, {%4,%5,%6,%7}, {%8,%9}, {%0,%1,%2,%3};"
        : "+f"(d[0]), "+f"(d[1]), "+f"(d[2]), "+f"(d[3])
        : "r"(a[0]), "r"(a[1]), "r"(a[2]), "r"(a[3]), "r"(b[0]), "r"(b[1]));
}

// ---------------------------------------------------------------------------
// Universal tf32 MMA GEMM:  C = A(M x K, K-major) * B(N x K, K-major)^T
// Block tile 128 x N_TILE, BK = 32, 256 threads.
// SMEM holds tiles pre-permuted into mma fragment layout:
//   A atom (16m x 8k) -> 32 lanes x 4 slots (ld.shared.v4 per fragment)
//   B atom ( 8n x 8k) -> 32 lanes x 2 slots (ld.shared.v2 per fragment)
// EPI: 0 = split-heads Q/K (+bias), 1 = V transposed (+bias),
//      2 = plain row-major (+bias), 3 = scores (*0.125), 4 = ctx scatter
// ---------------------------------------------------------------------------
template <int N_TILE, int EPI>
__global__ void __launch_bounds__(256) mma_gemm(
    const float* __restrict__ A, const float* __restrict__ B,
    const float* __restrict__ bias, float* __restrict__ C,
    int K, int lda, int ldb, long long strideA, long long strideB)
{
    constexpr int WN  = N_TILE / 64;     // warps along n  (2 or 1)
    constexpr int IM  = WN;              // m-atoms per warp (2 or 1)
    constexpr int BIT = N_TILE / 32;     // B float4 loads per thread (4 or 2)
    constexpr int NAT = N_TILE / 8;      // n atoms per k-atom row
    constexpr int A_FLOATS = 128 * 32;
    constexpr int B_FLOATS = N_TILE * 32;

    extern __shared__ float smf[];
    float* As = smf;                     // 2 buffers
    float* Bs = smf + 2 * A_FLOATS;

    const int tid = threadIdx.x;
    const int wid = tid >> 5, lid = tid & 31;
    const int warp_m = wid / WN, warp_n = wid % WN;
    const int bm = blockIdx.y * 128;
    const int bn = blockIdx.x * N_TILE;
    const int z  = blockIdx.z;

    const float* Ab = A + (size_t)z * strideA + (size_t)bm * lda;
    const float* Bb = B + (size_t)z * strideB + (size_t)bn * ldb;

    float4 ra[4];
    float4 rb[BIT];

    auto ldg_tiles = [&](int k0) {
#pragma unroll
        for (int it = 0; it < 4; it++) {
            int f = tid + it * 256;
            int row = f >> 3, k4 = f & 7;
            ra[it] = *(const float4*)(Ab + (size_t)row * lda + k0 + k4 * 4);
        }
#pragma unroll
        for (int it = 0; it < BIT; it++) {
            int f = tid + it * 256;
            int row = f >> 3, k4 = f & 7;
            rb[it] = *(const float4*)(Bb + (size_t)row * ldb + k0 + k4 * 4);
        }
    };

    auto sts_tiles = [&](int buf) {
        float* da = As + buf * A_FLOATS;
#pragma unroll
        for (int it = 0; it < 4; it++) {
            int f = tid + it * 256;
            int row = f >> 3, k4 = f & 7;
            int m_atom = row >> 4, r = row & 15;
            int k_atom = k4 >> 1;
            int slot = ((k4 & 1) << 1) | (r >> 3);
            int lane0 = (r & 7) << 2;
            float* p = da + ((k_atom * 8 + m_atom) * 128 + lane0 * 4 + slot);
            p[0]  = __uint_as_float(rn_tf32(ra[it].x));
            p[4]  = __uint_as_float(rn_tf32(ra[it].y));
            p[8]  = __uint_as_float(rn_tf32(ra[it].z));
            p[12] = __uint_as_float(rn_tf32(ra[it].w));
        }
        float* db = Bs + buf * B_FLOATS;
#pragma unroll
        for (int it = 0; it < BIT; it++) {
            int f = tid + it * 256;
            int row = f >> 3, k4 = f & 7;
            int n_atom = row >> 3, nn = row & 7;
            int k_atom = k4 >> 1;
            int slot = k4 & 1;
            int lane0 = nn << 2;
            float* p = db + ((k_atom * NAT + n_atom) * 64 + lane0 * 2 + slot);
            p[0] = __uint_as_float(rn_tf32(rb[it].x));
            p[2] = __uint_as_float(rn_tf32(rb[it].y));
            p[4] = __uint_as_float(rn_tf32(rb[it].z));
            p[6] = __uint_as_float(rn_tf32(rb[it].w));
        }
    };

    float acc[IM][8][4];
#pragma unroll
    for (int im = 0; im < IM; im++)
#pragma unroll
        for (int in = 0; in < 8; in++)
#pragma unroll
            for (int c = 0; c < 4; c++) acc[im][in][c] = 0.f;

    const int KS = K >> 5;

    // Prologue: stage tile0, prefetch tile1
    ldg_tiles(0);
    sts_tiles(0);
    if (KS > 1) ldg_tiles(32);
    __syncthreads();

    for (int ks = 0; ks < KS; ks++) {
        if (ks + 1 < KS) sts_tiles((ks + 1) & 1);
        if (ks + 2 < KS) ldg_tiles((ks + 2) << 5);

        const float* Ad = As + (ks & 1) * A_FLOATS;
        const float* Bd = Bs + (ks & 1) * B_FLOATS;
#pragma unroll
        for (int ka = 0; ka < 4; ka++) {
            uint32_t afr[IM][4];
#pragma unroll
            for (int im = 0; im < IM; im++) {
                const float4 v = *(const float4*)(Ad + (ka * 8 + warp_m * IM + im) * 128 + lid * 4);
                afr[im][0] = __float_as_uint(v.x); afr[im][1] = __float_as_uint(v.y);
                afr[im][2] = __float_as_uint(v.z); afr[im][3] = __float_as_uint(v.w);
            }
            uint32_t bfr[8][2];
#pragma unroll
            for (int in = 0; in < 8; in++) {
                const float2 v = *(const float2*)(Bd + (ka * NAT + warp_n * 8 + in) * 64 + lid * 2);
                bfr[in][0] = __float_as_uint(v.x); bfr[in][1] = __float_as_uint(v.y);
            }
#pragma unroll
            for (int im = 0; im < IM; im++)
#pragma unroll
                for (int in = 0; in < 8; in++)
                    mma_tf32(acc[im][in], afr[im], bfr[in]);
        }
        __syncthreads();
    }

    // -------------------------- Epilogue (direct from fragments) ----------
    const int g = lid >> 2, cq = lid & 3;
#pragma unroll
    for (int im = 0; im < IM; im++) {
        const int mbase = bm + warp_m * (IM * 16) + im * 16 + g;
#pragma unroll
        for (int in = 0; in < 8; in++) {
            const int n0 = bn + warp_n * 64 + in * 8 + cq * 2;
            const float c0 = acc[im][in][0], c1 = acc[im][in][1];
            const float c2 = acc[im][in][2], c3 = acc[im][in][3];
            if (EPI == 0) {
                const float2 bv = *(const float2*)(bias + n0);
                const int h = n0 >> 6, d = n0 & 63;
#pragma unroll
                for (int rr = 0; rr < 2; rr++) {
                    const int m = mbase + rr * 8;
                    const int b = m >> 11, s = m & 2047;
                    float2 o; o.x = (rr ? c2 : c0) + bv.x; o.y = (rr ? c3 : c1) + bv.y;
                    *(float2*)&C[(((size_t)(b * NUM_HEADS + h) * SEQ) + s) * D_K + d] = o;
                }
            } else if (EPI == 1) {
                const float b0 = bias[n0], b1 = bias[n0 + 1];
                const int h = n0 >> 6, d = n0 & 63;
#pragma unroll
                for (int rr = 0; rr < 2; rr++) {
                    const int m = mbase + rr * 8;
                    const int b = m >> 11, s = m & 2047;
                    const size_t base = ((size_t)(b * NUM_HEADS + h) * D_K + d) * SEQ + s;
                    C[base]       = (rr ? c2 : c0) + b0;
                    C[base + SEQ] = (rr ? c3 : c1) + b1;
                }
            } else if (EPI == 2) {
                const float2 bv = *(const float2*)(bias + n0);
#pragma unroll
                for (int rr = 0; rr < 2; rr++) {
                    const int m = mbase + rr * 8;
                    float2 o; o.x = (rr ? c2 : c0) + bv.x; o.y = (rr ? c3 : c1) + bv.y;
                    *(float2*)&C[(size_t)m * D_MODEL + n0] = o;
                }
            } else if (EPI == 3) {
#pragma unroll
                for (int rr = 0; rr < 2; rr++) {
                    const int m = mbase + rr * 8;
                    float2 o; o.x = (rr ? c2 : c0) * 0.125f; o.y = (rr ? c3 : c1) * 0.125f;
                    *(float2*)&C[(size_t)z * SEQ * SEQ + (size_t)m * SEQ + n0] = o;
                }
            } else {  // EPI == 4: ctx scatter
                const int b = z >> 4, h = z & 15;
#pragma unroll
                for (int rr = 0; rr < 2; rr++) {
                    const int m = mbase + rr * 8;
                    float2 o; o.x = (rr ? c2 : c0); o.y = (rr ? c3 : c1);
                    *(float2*)&C[((size_t)(b * SEQ + m)) * D_MODEL + h * D_K + n0] = o;
                }
            }
        }
    }
}

// ---------------------------------------------------------------------------
// Row softmax in place. One block (256 threads) per row of length 2048.
// ---------------------------------------------------------------------------
__global__ void softmax_kernel(float* __restrict__ attn) {
    const size_t row = blockIdx.x;
    float* p = attn + row * SEQ;
    const int tid = threadIdx.x;

    float v[8];
#pragma unroll
    for (int i = 0; i < 8; i++) v[i] = p[tid + i * 256];

    float m = v[0];
#pragma unroll
    for (int i = 1; i < 8; i++) m = fmaxf(m, v[i]);

    __shared__ float red[32];
#pragma unroll
    for (int o = 16; o > 0; o >>= 1) m = fmaxf(m, __shfl_xor_sync(0xffffffffu, m, o));
    if ((tid & 31) == 0) red[tid >> 5] = m;
    __syncthreads();
    if (tid < 32) {
        float t = (tid < 8) ? red[tid] : -1e30f;
#pragma unroll
        for (int o = 4; o > 0; o >>= 1) t = fmaxf(t, __shfl_xor_sync(0xffffffffu, t, o));
        if (tid == 0) red[0] = t;
    }
    __syncthreads();
    m = red[0];

    float s = 0.f;
#pragma unroll
    for (int i = 0; i < 8; i++) {
        v[i] = __expf(v[i] - m);
        s += v[i];
    }
#pragma unroll
    for (int o = 16; o > 0; o >>= 1) s += __shfl_xor_sync(0xffffffffu, s, o);
    __syncthreads();
    if ((tid & 31) == 0) red[tid >> 5] = s;
    __syncthreads();
    if (tid < 32) {
        float t = (tid < 8) ? red[tid] : 0.f;
#pragma unroll
        for (int o = 4; o > 0; o >>= 1) t += __shfl_xor_sync(0xffffffffu, t, o);
        if (tid == 0) red[0] = t;
    }
    __syncthreads();
    float inv = 1.f / red[0];

#pragma unroll
    for (int i = 0; i < 8; i++) p[tid + i * 256] = v[i] * inv;
}

extern "C" void kernel_launch(void* const* d_in, const int* in_sizes, int n_in,
                              void* d_out, int out_size) {
    const float* Q  = (const float*)d_in[0];
    const float* K  = (const float*)d_in[1];
    const float* V  = (const float*)d_in[2];
    const float* Wq = (const float*)d_in[3];
    const float* bq = (const float*)d_in[4];
    const float* Wk = (const float*)d_in[5];
    const float* bk = (const float*)d_in[6];
    const float* Wv = (const float*)d_in[7];
    const float* bv = (const float*)d_in[8];
    const float* Wo = (const float*)d_in[9];
    const float* bo = (const float*)d_in[10];

    float* out = (float*)d_out;

    const size_t OUT_ELEMS  = (size_t)M_ROWS * D_MODEL;
    const size_t ATTN_ELEMS = (size_t)BH * SEQ * SEQ;

    float* attn;
    if ((size_t)out_size >= OUT_ELEMS + ATTN_ELEMS) {
        attn = out + OUT_ELEMS;
    } else {
        void* p = nullptr;
        cudaGetSymbolAddress(&p, g_attn_fb);
        attn = (float*)p;
    }

    float *qp, *kp, *vtp, *cp;
    { void* t; cudaGetSymbolAddress(&t, g_q);   qp  = (float*)t; }
    { void* t; cudaGetSymbolAddress(&t, g_k);   kp  = (float*)t; }
    { void* t; cudaGetSymbolAddress(&t, g_vt);  vtp = (float*)t; }
    { void* t; cudaGetSymbolAddress(&t, g_ctx); cp  = (float*)t; }

    const int SM128 = 2 * (128 * 32) * 4 + 2 * (128 * 32) * 4;  // 65536
    const int SM64  = 2 * (128 * 32) * 4 + 2 * (64 * 32) * 4;   // 49152

    cudaFuncSetAttribute(mma_gemm<128, 0>, cudaFuncAttributeMaxDynamicSharedMemorySize, SM128);
    cudaFuncSetAttribute(mma_gemm<128, 1>, cudaFuncAttributeMaxDynamicSharedMemorySize, SM128);
    cudaFuncSetAttribute(mma_gemm<128, 2>, cudaFuncAttributeMaxDynamicSharedMemorySize, SM128);
    cudaFuncSetAttribute(mma_gemm<128, 3>, cudaFuncAttributeMaxDynamicSharedMemorySize, SM128);
    cudaFuncSetAttribute(mma_gemm<64, 4>,  cudaFuncAttributeMaxDynamicSharedMemorySize, SM64);

    // Q/K/V projections (M=8192, N=1024, K=1024)
    dim3 projGrid(D_MODEL / 128, M_ROWS / 128, 1);  // (8, 64)
    mma_gemm<128, 0><<<projGrid, 256, SM128>>>(Q, Wq, bq, qp, 1024, 1024, 1024, 0, 0);
    mma_gemm<128, 0><<<projGrid, 256, SM128>>>(K, Wk, bk, kp, 1024, 1024, 1024, 0, 0);
    mma_gemm<128, 1><<<projGrid, 256, SM128>>>(V, Wv, bv, vtp, 1024, 1024, 1024, 0, 0);

    // Scores: per head, (2048 x 2048) = q (2048x64) @ k^T
    dim3 scoresGrid(SEQ / 128, SEQ / 128, BH);      // (16, 16, 64)
    mma_gemm<128, 3><<<scoresGrid, 256, SM128>>>(qp, kp, nullptr, attn,
                                                 64, 64, 64,
                                                 (long long)SEQ * D_K,
                                                 (long long)SEQ * D_K);

    softmax_kernel<<<(unsigned)((size_t)BH * SEQ), 256>>>(attn);

    // ctx: per head, (2048 x 64) = attn (2048x2048) @ vT(64x2048)^T
    dim3 ctxGrid(1, SEQ / 128, BH);                 // (1, 16, 64)
    mma_gemm<64, 4><<<ctxGrid, 256, SM64>>>(attn, vtp, nullptr, cp,
                                            SEQ, SEQ, SEQ,
                                            (long long)SEQ * SEQ,
                                            (long long)D_K * SEQ);

    // Output projection
    mma_gemm<128, 2><<<projGrid, 256, SM128>>>(cp, Wo, bo, out, 1024, 1024, 1024, 0, 0);
}

// round 4
// speedup vs baseline: 2.4825x; 1.1142x over previous
#include <cuda_runtime.h>
#include <cstdint>

#define D_MODEL 1024
#define NUM_HEADS 16
#define D_K 64
#define BATCH 4
#define SEQ 2048
#define BH (BATCH * NUM_HEADS)          // 64
#define M_ROWS (BATCH * SEQ)            // 8192

// Scratch (device globals; no dynamic allocation allowed)
__device__ float g_q[(size_t)BH * SEQ * D_K];
__device__ float g_k[(size_t)BH * SEQ * D_K];
__device__ float g_vt[(size_t)BH * D_K * SEQ];   // V transposed: [bh][d][s]
__device__ float g_ctx[(size_t)M_ROWS * D_MODEL];
__device__ float g_l[(size_t)BH * SEQ];          // softmax row sums
__device__ float g_attn_fb[(size_t)BH * SEQ * SEQ];

// Round fp32 -> tf32 (round-to-nearest; HMMA then truncates losslessly)
__device__ __forceinline__ uint32_t rn_tf32(float x) {
    return (__float_as_uint(x) + 0x1000u) & 0xFFFFE000u;
}

__device__ __forceinline__ void mma_tf32(float* d, const uint32_t* a, const uint32_t* b) {
    asm volatile(
        "mma.sync.aligned.m16n8k8.row.col.f32.tf32.tf32.f32 "
        "{%0,%1,%2,%3}, {%4,%5,%6,%7}, {%8,%9}, {%0,%1,%2,%3};"
        : "+f"(d[0]), "+f"(d[1]), "+f"(d[2]), "+f"(d[3])
        : "r"(a[0]), "r"(a[1]), "r"(a[2]), "r"(a[3]), "r"(b[0]), "r"(b[1]));
}

// Fragment smem block strides (padded to break STS bank conflicts)
#define ABLK 132   // 128 floats + 4 pad
#define BBLK 66    // 64 floats + 2 pad

// ---------------------------------------------------------------------------
// Projection GEMM:  C = A(M x K, K-major) * B(N x K, K-major)^T   (tf32 MMA)
// Block tile 128 x 128, BK = 32, 256 threads, warps 4x2.
// EPI: 0 = split-heads Q/K (+bias), 1 = V transposed (+bias), 2 = row-major (+bias)
// ---------------------------------------------------------------------------
template <int EPI>
__global__ void __launch_bounds__(256) mma_gemm(
    const float* __restrict__ A, const float* __restrict__ B,
    const float* __restrict__ bias, float* __restrict__ C,
    int K, int lda, int ldb)
{
    constexpr int A_FLOATS = 32 * ABLK;   // ka4 x ma8 blocks
    constexpr int B_FLOATS = 64 * BBLK;   // ka4 x na16 blocks

    extern __shared__ float smf[];
    float* As = smf;
    float* Bs = smf + 2 * A_FLOATS;

    const int tid = threadIdx.x;
    const int wid = tid >> 5, lid = tid & 31;
    const int warp_m = wid >> 1, warp_n = wid & 1;
    const int bm = blockIdx.y * 128;
    const int bn = blockIdx.x * 128;

    const float* Ab = A + (size_t)bm * lda;
    const float* Bb = B + (size_t)bn * ldb;

    float4 ra[4], rb[4];

    auto ldg_tiles = [&](int k0) {
#pragma unroll
        for (int it = 0; it < 4; it++) {
            int f = tid + it * 256;
            int row = f >> 3, k4 = f & 7;
            ra[it] = *(const float4*)(Ab + (size_t)row * lda + k0 + k4 * 4);
            rb[it] = *(const float4*)(Bb + (size_t)row * ldb + k0 + k4 * 4);
        }
    };

    auto sts_tiles = [&](int buf) {
        float* da = As + buf * A_FLOATS;
        float* db = Bs + buf * B_FLOATS;
#pragma unroll
        for (int it = 0; it < 4; it++) {
            int f = tid + it * 256;
            int row = f >> 3, k4 = f & 7;
            {
                int ma = row >> 4, r = row & 15;
                int ka = k4 >> 1;
                int slot = ((k4 & 1) << 1) | (r >> 3);
                float* p = da + ((ka * 8 + ma) * ABLK + ((r & 7) << 4) + slot);
                p[0]  = __uint_as_float(rn_tf32(ra[it].x));
                p[4]  = __uint_as_float(rn_tf32(ra[it].y));
                p[8]  = __uint_as_float(rn_tf32(ra[it].z));
                p[12] = __uint_as_float(rn_tf32(ra[it].w));
            }
            {
                int na = row >> 3, nn = row & 7;
                int ka = k4 >> 1;
                int slot = k4 & 1;
                float* p = db + ((ka * 16 + na) * BBLK + (nn << 3) + slot);
                p[0] = __uint_as_float(rn_tf32(rb[it].x));
                p[2] = __uint_as_float(rn_tf32(rb[it].y));
                p[4] = __uint_as_float(rn_tf32(rb[it].z));
                p[6] = __uint_as_float(rn_tf32(rb[it].w));
            }
        }
    };

    float acc[2][8][4];
#pragma unroll
    for (int im = 0; im < 2; im++)
#pragma unroll
        for (int in = 0; in < 8; in++)
#pragma unroll
            for (int c = 0; c < 4; c++) acc[im][in][c] = 0.f;

    const int KS = K >> 5;
    ldg_tiles(0);
    sts_tiles(0);
    ldg_tiles(32);
    __syncthreads();

    for (int ks = 0; ks < KS; ks++) {
        if (ks + 1 < KS) sts_tiles((ks + 1) & 1);
        if (ks + 2 < KS) ldg_tiles((ks + 2) << 5);

        const float* Ad = As + (ks & 1) * A_FLOATS;
        const float* Bd = Bs + (ks & 1) * B_FLOATS;
#pragma unroll
        for (int ka = 0; ka < 4; ka++) {
            uint32_t afr[2][4];
#pragma unroll
            for (int im = 0; im < 2; im++) {
                const float4 v = *(const float4*)(Ad + (ka * 8 + warp_m * 2 + im) * ABLK + lid * 4);
                afr[im][0] = __float_as_uint(v.x); afr[im][1] = __float_as_uint(v.y);
                afr[im][2] = __float_as_uint(v.z); afr[im][3] = __float_as_uint(v.w);
            }
            uint32_t bfr[8][2];
#pragma unroll
            for (int in = 0; in < 8; in++) {
                const float2 v = *(const float2*)(Bd + (ka * 16 + warp_n * 8 + in) * BBLK + lid * 2);
                bfr[in][0] = __float_as_uint(v.x); bfr[in][1] = __float_as_uint(v.y);
            }
#pragma unroll
            for (int im = 0; im < 2; im++)
#pragma unroll
                for (int in = 0; in < 8; in++)
                    mma_tf32(acc[im][in], afr[im], bfr[in]);
        }
        __syncthreads();
    }

    const int g = lid >> 2, cq = lid & 3;
#pragma unroll
    for (int im = 0; im < 2; im++) {
        const int mbase = bm + warp_m * 32 + im * 16 + g;
#pragma unroll
        for (int in = 0; in < 8; in++) {
            const int n0 = bn + warp_n * 64 + in * 8 + cq * 2;
            const float c0 = acc[im][in][0], c1 = acc[im][in][1];
            const float c2 = acc[im][in][2], c3 = acc[im][in][3];
            if (EPI == 0) {
                const float2 bv = *(const float2*)(bias + n0);
                const int h = n0 >> 6, d = n0 & 63;
#pragma unroll
                for (int rr = 0; rr < 2; rr++) {
                    const int m = mbase + rr * 8;
                    const int b = m >> 11, s = m & 2047;
                    float2 o; o.x = (rr ? c2 : c0) + bv.x; o.y = (rr ? c3 : c1) + bv.y;
                    *(float2*)&C[(((size_t)(b * NUM_HEADS + h) * SEQ) + s) * D_K + d] = o;
                }
            } else if (EPI == 1) {
                const float b0 = bias[n0], b1 = bias[n0 + 1];
                const int h = n0 >> 6, d = n0 & 63;
#pragma unroll
                for (int rr = 0; rr < 2; rr++) {
                    const int m = mbase + rr * 8;
                    const int b = m >> 11, s = m & 2047;
                    const size_t base = ((size_t)(b * NUM_HEADS + h) * D_K + d) * SEQ + s;
                    C[base]       = (rr ? c2 : c0) + b0;
                    C[base + SEQ] = (rr ? c3 : c1) + b1;
                }
            } else {
                const float2 bv = *(const float2*)(bias + n0);
#pragma unroll
                for (int rr = 0; rr < 2; rr++) {
                    const int m = mbase + rr * 8;
                    float2 o; o.x = (rr ? c2 : c0) + bv.x; o.y = (rr ? c3 : c1) + bv.y;
                    *(float2*)&C[(size_t)m * D_MODEL + n0] = o;
                }
            }
        }
    }
}

// ---------------------------------------------------------------------------
// flashA: per (m-tile 128, head) block — fused scores + exp + row-sum + ctx.
// No attention tensor traffic. Writes g_ctx and g_l.
// smem layout (floats): Q[64*ABLK] | K0,K1[128*BBLK each... see offsets]
// ---------------------------------------------------------------------------
#define FA_Q    0
#define FA_K0   (64 * ABLK)                  // 8448
#define FA_KB   (128 * BBLK)                 // 8448 per k-buffer (ka8 x na16)
#define FA_P    (FA_K0 + 2 * FA_KB)          // 25344
#define FA_V    (FA_P + 128 * ABLK)          // 42240 (ka16 x na8 of BBLK)
#define FA_PART (FA_V + 128 * BBLK)          // 50688
#define FA_LSUM (FA_PART + 256)              // 50944
#define FA_TOT  (FA_LSUM + 128)              // 51072 floats = 204288 B

__global__ void __launch_bounds__(256) flash_kernel()
{
    extern __shared__ float smf[];
    const int tid = threadIdx.x;
    const int wid = tid >> 5, lid = tid & 31;
    const int warp_m = wid >> 1, warp_n = wid & 1;
    const int g = lid >> 2, cq = lid & 3;
    const int bm = blockIdx.x * 128;
    const int bh = blockIdx.y;

    const float* qp = g_q + (size_t)bh * SEQ * D_K + (size_t)bm * D_K;
    const float* kp = g_k + (size_t)bh * SEQ * D_K;
    const float* vp = g_vt + (size_t)bh * D_K * SEQ;

    // ---- load Q tile into A-frag layout (rows 128 x k 64) ----
#pragma unroll
    for (int it = 0; it < 8; it++) {
        int f = tid + it * 256;
        int row = f >> 4, c4 = f & 15;
        float4 v = *(const float4*)(qp + (size_t)row * D_K + c4 * 4);
        int ma = row >> 4, r = row & 15;
        int ka = c4 >> 1;
        int slot = ((c4 & 1) << 1) | (r >> 3);
        float* p = smf + FA_Q + ((ka * 8 + ma) * ABLK + ((r & 7) << 4) + slot);
        p[0]  = __uint_as_float(rn_tf32(v.x));
        p[4]  = __uint_as_float(rn_tf32(v.y));
        p[8]  = __uint_as_float(rn_tf32(v.z));
        p[12] = __uint_as_float(rn_tf32(v.w));
    }

    float4 rk[8];
    auto ldg_k = [&](int t) {
        const float* kb = kp + (size_t)(t * 128) * D_K;
#pragma unroll
        for (int it = 0; it < 8; it++) {
            int f = tid + it * 256;
            int row = f >> 4, c4 = f & 15;
            rk[it] = *(const float4*)(kb + (size_t)row * D_K + c4 * 4);
        }
    };
    auto sts_k = [&](int buf) {
        float* db = smf + FA_K0 + buf * FA_KB;
#pragma unroll
        for (int it = 0; it < 8; it++) {
            int f = tid + it * 256;
            int row = f >> 4, c4 = f & 15;
            int na = row >> 3, nn = row & 7;
            int ka = c4 >> 1, slot = c4 & 1;
            float* p = db + ((ka * 16 + na) * BBLK + (nn << 3) + slot);
            p[0] = __uint_as_float(rn_tf32(rk[it].x));
            p[2] = __uint_as_float(rn_tf32(rk[it].y));
            p[4] = __uint_as_float(rn_tf32(rk[it].z));
            p[6] = __uint_as_float(rn_tf32(rk[it].w));
        }
    };

    float acc2[8][4];
#pragma unroll
    for (int in = 0; in < 8; in++)
#pragma unroll
        for (int c = 0; c < 4; c++) acc2[in][c] = 0.f;
    float racc[2][2] = {{0.f, 0.f}, {0.f, 0.f}};

    ldg_k(0); sts_k(0); ldg_k(1);
    __syncthreads();

    for (int t = 0; t < 16; t++) {
        if (t + 1 < 16) sts_k((t + 1) & 1);
        if (t + 2 < 16) ldg_k(t + 2);

        // ---- scores MMA: Q(128x64) x K_tile(128x64)^T ----
        float acc[2][8][4];
#pragma unroll
        for (int im = 0; im < 2; im++)
#pragma unroll
            for (int in = 0; in < 8; in++)
#pragma unroll
                for (int c = 0; c < 4; c++) acc[im][in][c] = 0.f;

        const float* Kd = smf + FA_K0 + (t & 1) * FA_KB;
#pragma unroll
        for (int ka = 0; ka < 8; ka++) {
            uint32_t afr[2][4];
#pragma unroll
            for (int im = 0; im < 2; im++) {
                const float4 v = *(const float4*)(smf + FA_Q + (ka * 8 + warp_m * 2 + im) * ABLK + lid * 4);
                afr[im][0] = __float_as_uint(v.x); afr[im][1] = __float_as_uint(v.y);
                afr[im][2] = __float_as_uint(v.z); afr[im][3] = __float_as_uint(v.w);
            }
            uint32_t bfr[8][2];
#pragma unroll
            for (int in = 0; in < 8; in++) {
                const float2 v = *(const float2*)(Kd + (ka * 16 + warp_n * 8 + in) * BBLK + lid * 2);
                bfr[in][0] = __float_as_uint(v.x); bfr[in][1] = __float_as_uint(v.y);
            }
#pragma unroll
            for (int im = 0; im < 2; im++)
#pragma unroll
                for (int in = 0; in < 8; in++)
                    mma_tf32(acc[im][in], afr[im], bfr[in]);
        }

        // ---- e = exp(s/8); accumulate row sums; scatter to P-frag ----
#pragma unroll
        for (int im = 0; im < 2; im++) {
            const int row0 = warp_m * 32 + im * 16 + g;
#pragma unroll
            for (int in = 0; in < 8; in++) {
                const int col0 = warp_n * 64 + in * 8 + cq * 2;
#pragma unroll
                for (int c = 0; c < 4; c++) {
                    const int rr = c >> 1, j2 = c & 1;
                    const float e = __expf(acc[im][in][c] * 0.125f);
                    racc[im][rr] += e;
                    const int rowl = row0 + rr * 8;
                    const int col = col0 + j2;
                    const int blk = (col >> 3) * 8 + (rowl >> 4);
                    const int idx = blk * ABLK + (rowl & 7) * 16 + (col & 3) * 4 +
                                    (((col >> 2) & 1) << 1) + ((rowl >> 3) & 1);
                    smf[FA_P + idx] = __uint_as_float(rn_tf32(e));
                }
            }
        }

        // ---- load V tile (64 d-rows x 128 s) into B-frag ----
        {
            const float* vb = vp + t * 128;
#pragma unroll
            for (int it = 0; it < 8; it++) {
                int f = tid + it * 256;
                int row = f >> 5, c4 = f & 31;
                float4 v = *(const float4*)(vb + (size_t)row * SEQ + c4 * 4);
                int na = row >> 3, nn = row & 7;
                int ka = c4 >> 1, slot = c4 & 1;
                float* p = smf + FA_V + ((ka * 8 + na) * BBLK + (nn << 3) + slot);
                p[0] = __uint_as_float(rn_tf32(v.x));
                p[2] = __uint_as_float(rn_tf32(v.y));
                p[4] = __uint_as_float(rn_tf32(v.z));
                p[6] = __uint_as_float(rn_tf32(v.w));
            }
        }
        __syncthreads();

        // ---- ctx MMA: P(128x128) x Vt(64x128)^T, warp = 16 rows ----
#pragma unroll
        for (int ka = 0; ka < 16; ka++) {
            uint32_t afr[4];
            {
                const float4 v = *(const float4*)(smf + FA_P + (ka * 8 + wid) * ABLK + lid * 4);
                afr[0] = __float_as_uint(v.x); afr[1] = __float_as_uint(v.y);
                afr[2] = __float_as_uint(v.z); afr[3] = __float_as_uint(v.w);
            }
#pragma unroll
            for (int in = 0; in < 8; in++) {
                uint32_t bfr[2];
                const float2 v = *(const float2*)(smf + FA_V + (ka * 8 + in) * BBLK + lid * 2);
                bfr[0] = __float_as_uint(v.x); bfr[1] = __float_as_uint(v.y);
                mma_tf32(acc2[in], afr, bfr);
            }
        }
        __syncthreads();
    }

    // ---- finalize row sums (deterministic reduction) ----
#pragma unroll
    for (int im = 0; im < 2; im++)
#pragma unroll
        for (int rr = 0; rr < 2; rr++) {
            float s = racc[im][rr];
            s += __shfl_xor_sync(0xffffffffu, s, 1);
            s += __shfl_xor_sync(0xffffffffu, s, 2);
            if (cq == 0)
                smf[FA_PART + warp_n * 128 + warp_m * 32 + im * 16 + rr * 8 + g] = s;
        }
    __syncthreads();
    if (tid < 128) {
        float l = smf[FA_PART + tid] + smf[FA_PART + 128 + tid];
        smf[FA_LSUM + tid] = l;
        g_l[(size_t)bh * SEQ + bm + tid] = l;
    }
    __syncthreads();

    // ---- ctx epilogue: scale by 1/l, scatter to g_ctx ----
    const int b = bh >> 4, h = bh & 15;
#pragma unroll
    for (int rr = 0; rr < 2; rr++) {
        const int rowl = wid * 16 + g + rr * 8;
        const float inv = 1.f / smf[FA_LSUM + rowl];
        const int srow = bm + rowl;
#pragma unroll
        for (int in = 0; in < 8; in++) {
            const int n0 = in * 8 + cq * 2;
            float2 o;
            o.x = acc2[in][rr ? 2 : 0] * inv;
            o.y = acc2[in][rr ? 3 : 1] * inv;
            *(float2*)&g_ctx[((size_t)(b * SEQ + srow)) * D_MODEL + h * D_K + n0] = o;
        }
    }
}

// ---------------------------------------------------------------------------
// attnW: recompute scores, write attn = exp(s/8) / l.  Write-once (1.07 GB).
// ---------------------------------------------------------------------------
#define AW_Q   0
#define AW_K0  (64 * ABLK)
#define AW_INV (AW_K0 + 2 * FA_KB)
#define AW_TOT (AW_INV + 128)     // 25472 floats

__global__ void __launch_bounds__(256) attnw_kernel(float* __restrict__ attn)
{
    extern __shared__ float smf[];
    const int tid = threadIdx.x;
    const int wid = tid >> 5, lid = tid & 31;
    const int warp_m = wid >> 1, warp_n = wid & 1;
    const int g = lid >> 2, cq = lid & 3;
    const int bm = blockIdx.x * 128;
    const int bh = blockIdx.y;

    const float* qp = g_q + (size_t)bh * SEQ * D_K + (size_t)bm * D_K;
    const float* kp = g_k + (size_t)bh * SEQ * D_K;
    float* ap = attn + (size_t)bh * SEQ * SEQ;

    if (tid < 128)
        smf[AW_INV + tid] = 1.f / g_l[(size_t)bh * SEQ + bm + tid];

#pragma unroll
    for (int it = 0; it < 8; it++) {
        int f = tid + it * 256;
        int row = f >> 4, c4 = f & 15;
        float4 v = *(const float4*)(qp + (size_t)row * D_K + c4 * 4);
        int ma = row >> 4, r = row & 15;
        int ka = c4 >> 1;
        int slot = ((c4 & 1) << 1) | (r >> 3);
        float* p = smf + AW_Q + ((ka * 8 + ma) * ABLK + ((r & 7) << 4) + slot);
        p[0]  = __uint_as_float(rn_tf32(v.x));
        p[4]  = __uint_as_float(rn_tf32(v.y));
        p[8]  = __uint_as_float(rn_tf32(v.z));
        p[12] = __uint_as_float(rn_tf32(v.w));
    }

    float4 rk[8];
    auto ldg_k = [&](int t) {
        const float* kb = kp + (size_t)(t * 128) * D_K;
#pragma unroll
        for (int it = 0; it < 8; it++) {
            int f = tid + it * 256;
            int row = f >> 4, c4 = f & 15;
            rk[it] = *(const float4*)(kb + (size_t)row * D_K + c4 * 4);
        }
    };
    auto sts_k = [&](int buf) {
        float* db = smf + AW_K0 + buf * FA_KB;
#pragma unroll
        for (int it = 0; it < 8; it++) {
            int f = tid + it * 256;
            int row = f >> 4, c4 = f & 15;
            int na = row >> 3, nn = row & 7;
            int ka = c4 >> 1, slot = c4 & 1;
            float* p = db + ((ka * 16 + na) * BBLK + (nn << 3) + slot);
            p[0] = __uint_as_float(rn_tf32(rk[it].x));
            p[2] = __uint_as_float(rn_tf32(rk[it].y));
            p[4] = __uint_as_float(rn_tf32(rk[it].z));
            p[6] = __uint_as_float(rn_tf32(rk[it].w));
        }
    };

    ldg_k(0); sts_k(0); ldg_k(1);
    __syncthreads();

    const int row0q = warp_m * 32 + g;
    const float inv0 = smf[AW_INV + row0q];
    const float inv8 = smf[AW_INV + row0q + 8];
    const float inv16 = smf[AW_INV + row0q + 16];
    const float inv24 = smf[AW_INV + row0q + 24];

    for (int t = 0; t < 16; t++) {
        if (t + 1 < 16) sts_k((t + 1) & 1);
        if (t + 2 < 16) ldg_k(t + 2);

        float acc[2][8][4];
#pragma unroll
        for (int im = 0; im < 2; im++)
#pragma unroll
            for (int in = 0; in < 8; in++)
#pragma unroll
                for (int c = 0; c < 4; c++) acc[im][in][c] = 0.f;

        const float* Kd = smf + AW_K0 + (t & 1) * FA_KB;
#pragma unroll
        for (int ka = 0; ka < 8; ka++) {
            uint32_t afr[2][4];
#pragma unroll
            for (int im = 0; im < 2; im++) {
                const float4 v = *(const float4*)(smf + AW_Q + (ka * 8 + warp_m * 2 + im) * ABLK + lid * 4);
                afr[im][0] = __float_as_uint(v.x); afr[im][1] = __float_as_uint(v.y);
                afr[im][2] = __float_as_uint(v.z); afr[im][3] = __float_as_uint(v.w);
            }
            uint32_t bfr[8][2];
#pragma unroll
            for (int in = 0; in < 8; in++) {
                const float2 v = *(const float2*)(Kd + (ka * 16 + warp_n * 8 + in) * BBLK + lid * 2);
                bfr[in][0] = __float_as_uint(v.x); bfr[in][1] = __float_as_uint(v.y);
            }
#pragma unroll
            for (int im = 0; im < 2; im++)
#pragma unroll
                for (int in = 0; in < 8; in++)
                    mma_tf32(acc[im][in], afr[im], bfr[in]);
        }

#pragma unroll
        for (int im = 0; im < 2; im++) {
            const int mrow = bm + warp_m * 32 + im * 16 + g;
            const float iv0 = im ? inv16 : inv0;
            const float iv1 = im ? inv24 : inv8;
#pragma unroll
            for (int in = 0; in < 8; in++) {
                const int n0 = t * 128 + warp_n * 64 + in * 8 + cq * 2;
                float2 o0, o1;
                o0.x = __expf(acc[im][in][0] * 0.125f) * iv0;
                o0.y = __expf(acc[im][in][1] * 0.125f) * iv0;
                o1.x = __expf(acc[im][in][2] * 0.125f) * iv1;
                o1.y = __expf(acc[im][in][3] * 0.125f) * iv1;
                *(float2*)&ap[(size_t)mrow * SEQ + n0] = o0;
                *(float2*)&ap[(size_t)(mrow + 8) * SEQ + n0] = o1;
            }
        }
        __syncthreads();
    }
}

extern "C" void kernel_launch(void* const* d_in, const int* in_sizes, int n_in,
                              void* d_out, int out_size) {
    const float* Q  = (const float*)d_in[0];
    const float* K  = (const float*)d_in[1];
    const float* V  = (const float*)d_in[2];
    const float* Wq = (const float*)d_in[3];
    const float* bq = (const float*)d_in[4];
    const float* Wk = (const float*)d_in[5];
    const float* bk = (const float*)d_in[6];
    const float* Wv = (const float*)d_in[7];
    const float* bv = (const float*)d_in[8];
    const float* Wo = (const float*)d_in[9];
    const float* bo = (const float*)d_in[10];

    float* out = (float*)d_out;

    const size_t OUT_ELEMS  = (size_t)M_ROWS * D_MODEL;
    const size_t ATTN_ELEMS = (size_t)BH * SEQ * SEQ;

    float* attn;
    if ((size_t)out_size >= OUT_ELEMS + ATTN_ELEMS) {
        attn = out + OUT_ELEMS;
    } else {
        void* p = nullptr;
        cudaGetSymbolAddress(&p, g_attn_fb);
        attn = (float*)p;
    }

    float *qp, *kp, *vtp, *cp;
    { void* t; cudaGetSymbolAddress(&t, g_q);   qp  = (float*)t; }
    { void* t; cudaGetSymbolAddress(&t, g_k);   kp  = (float*)t; }
    { void* t; cudaGetSymbolAddress(&t, g_vt);  vtp = (float*)t; }
    { void* t; cudaGetSymbolAddress(&t, g_ctx); cp  = (float*)t; }

    const int SMP  = (2 * 32 * ABLK + 2 * 64 * BBLK) * 4;  // proj smem bytes
    const int SMFA = FA_TOT * 4;
    const int SMAW = AW_TOT * 4;

    cudaFuncSetAttribute(mma_gemm<0>, cudaFuncAttributeMaxDynamicSharedMemorySize, SMP);
    cudaFuncSetAttribute(mma_gemm<1>, cudaFuncAttributeMaxDynamicSharedMemorySize, SMP);
    cudaFuncSetAttribute(mma_gemm<2>, cudaFuncAttributeMaxDynamicSharedMemorySize, SMP);
    cudaFuncSetAttribute(flash_kernel, cudaFuncAttributeMaxDynamicSharedMemorySize, SMFA);
    cudaFuncSetAttribute(attnw_kernel, cudaFuncAttributeMaxDynamicSharedMemorySize, SMAW);

    dim3 projGrid(D_MODEL / 128, M_ROWS / 128);     // (8, 64)
    mma_gemm<0><<<projGrid, 256, SMP>>>(Q, Wq, bq, qp, 1024, 1024, 1024);
    mma_gemm<0><<<projGrid, 256, SMP>>>(K, Wk, bk, kp, 1024, 1024, 1024);
    mma_gemm<1><<<projGrid, 256, SMP>>>(V, Wv, bv, vtp, 1024, 1024, 1024);

    dim3 attGrid(SEQ / 128, BH);                    // (16, 64)
    flash_kernel<<<attGrid, 256, SMFA>>>();
    attnw_kernel<<<attGrid, 256, SMAW>>>(attn);

    mma_gemm<2><<<projGrid, 256, SMP>>>(cp, Wo, bo, out, 1024, 1024, 1024);
}

// round 5
// speedup vs baseline: 2.5002x; 1.0071x over previous
#include <cuda_runtime.h>
#include <cstdint>

#define D_MODEL 1024
#define NUM_HEADS 16
#define D_K 64
#define BATCH 4
#define SEQ 2048
#define BH (BATCH * NUM_HEADS)          // 64
#define M_ROWS (BATCH * SEQ)            // 8192

// Scratch (device globals; no dynamic allocation allowed)
__device__ float g_q[(size_t)BH * SEQ * D_K];
__device__ float g_k[(size_t)BH * SEQ * D_K];
__device__ float g_vt[(size_t)BH * D_K * SEQ];   // V transposed: [bh][d][s]
__device__ float g_ctx[(size_t)M_ROWS * D_MODEL];
__device__ float g_l[(size_t)BH * SEQ];          // softmax row sums
__device__ float g_attn_fb[(size_t)BH * SEQ * SEQ];

// Round fp32 -> tf32 (round-to-nearest; HMMA then truncates losslessly)
__device__ __forceinline__ uint32_t rn_tf32(float x) {
    return (__float_as_uint(x) + 0x1000u) & 0xFFFFE000u;
}

__device__ __forceinline__ void mma_tf32(float* d, const uint32_t* a, const uint32_t* b) {
    asm volatile(
        "mma.sync.aligned.m16n8k8.row.col.f32.tf32.tf32.f32 "
        "{%0,%1,%2,%3}, {%4,%5,%6,%7}, {%8,%9}, {%0,%1,%2,%3};"
        : "+f"(d[0]), "+f"(d[1]), "+f"(d[2]), "+f"(d[3])
        : "r"(a[0]), "r"(a[1]), "r"(a[2]), "r"(a[3]), "r"(b[0]), "r"(b[1]));
}

// Fragment smem block strides (padded to break STS bank conflicts)
#define ABLK 132   // 128 floats + 4 pad
#define BBLK 66    // 64 floats + 2 pad

// ---------------------------------------------------------------------------
// Projection GEMM:  C = A(M x K, K-major) * B(N x K, K-major)^T   (tf32 MMA)
// Block tile 128 x 128, BK = 32, 256 threads, warps 4x2, 2 CTAs/SM.
// EPI: 0 = split-heads Q/K (+bias), 1 = V transposed (+bias), 2 = row-major (+bias)
// ---------------------------------------------------------------------------
template <int EPI>
__global__ void __launch_bounds__(256, 2) mma_gemm(
    const float* __restrict__ A, const float* __restrict__ B,
    const float* __restrict__ bias, float* __restrict__ C,
    int K, int lda, int ldb)
{
    constexpr int A_FLOATS = 32 * ABLK;   // ka4 x ma8 blocks
    constexpr int B_FLOATS = 64 * BBLK;   // ka4 x na16 blocks

    extern __shared__ float smf[];
    float* As = smf;
    float* Bs = smf + 2 * A_FLOATS;

    const int tid = threadIdx.x;
    const int wid = tid >> 5, lid = tid & 31;
    const int warp_m = wid >> 1, warp_n = wid & 1;
    const int bm = blockIdx.y * 128;
    const int bn = blockIdx.x * 128;

    const float* Ab = A + (size_t)bm * lda;
    const float* Bb = B + (size_t)bn * ldb;

    float4 ra[4], rb[4];

    auto ldg_tiles = [&](int k0) {
#pragma unroll
        for (int it = 0; it < 4; it++) {
            int f = tid + it * 256;
            int row = f >> 3, k4 = f & 7;
            ra[it] = *(const float4*)(Ab + (size_t)row * lda + k0 + k4 * 4);
            rb[it] = *(const float4*)(Bb + (size_t)row * ldb + k0 + k4 * 4);
        }
    };

    auto sts_tiles = [&](int buf) {
        float* da = As + buf * A_FLOATS;
        float* db = Bs + buf * B_FLOATS;
#pragma unroll
        for (int it = 0; it < 4; it++) {
            int f = tid + it * 256;
            int row = f >> 3, k4 = f & 7;
            {
                int ma = row >> 4, r = row & 15;
                int ka = k4 >> 1;
                int slot = ((k4 & 1) << 1) | (r >> 3);
                float* p = da + ((ka * 8 + ma) * ABLK + ((r & 7) << 4) + slot);
                p[0]  = __uint_as_float(rn_tf32(ra[it].x));
                p[4]  = __uint_as_float(rn_tf32(ra[it].y));
                p[8]  = __uint_as_float(rn_tf32(ra[it].z));
                p[12] = __uint_as_float(rn_tf32(ra[it].w));
            }
            {
                int na = row >> 3, nn = row & 7;
                int ka = k4 >> 1;
                int slot = k4 & 1;
                float* p = db + ((ka * 16 + na) * BBLK + (nn << 3) + slot);
                p[0] = __uint_as_float(rn_tf32(rb[it].x));
                p[2] = __uint_as_float(rn_tf32(rb[it].y));
                p[4] = __uint_as_float(rn_tf32(rb[it].z));
                p[6] = __uint_as_float(rn_tf32(rb[it].w));
            }
        }
    };

    float acc[2][8][4];
#pragma unroll
    for (int im = 0; im < 2; im++)
#pragma unroll
        for (int in = 0; in < 8; in++)
#pragma unroll
            for (int c = 0; c < 4; c++) acc[im][in][c] = 0.f;

    const int KS = K >> 5;
    ldg_tiles(0);
    sts_tiles(0);
    ldg_tiles(32);
    __syncthreads();

    for (int ks = 0; ks < KS; ks++) {
        if (ks + 1 < KS) sts_tiles((ks + 1) & 1);
        if (ks + 2 < KS) ldg_tiles((ks + 2) << 5);

        const float* Ad = As + (ks & 1) * A_FLOATS;
        const float* Bd = Bs + (ks & 1) * B_FLOATS;
#pragma unroll
        for (int ka = 0; ka < 4; ka++) {
            uint32_t afr[2][4];
#pragma unroll
            for (int im = 0; im < 2; im++) {
                const float4 v = *(const float4*)(Ad + (ka * 8 + warp_m * 2 + im) * ABLK + lid * 4);
                afr[im][0] = __float_as_uint(v.x); afr[im][1] = __float_as_uint(v.y);
                afr[im][2] = __float_as_uint(v.z); afr[im][3] = __float_as_uint(v.w);
            }
            uint32_t bfr[8][2];
#pragma unroll
            for (int in = 0; in < 8; in++) {
                const float2 v = *(const float2*)(Bd + (ka * 16 + warp_n * 8 + in) * BBLK + lid * 2);
                bfr[in][0] = __float_as_uint(v.x); bfr[in][1] = __float_as_uint(v.y);
            }
#pragma unroll
            for (int im = 0; im < 2; im++)
#pragma unroll
                for (int in = 0; in < 8; in++)
                    mma_tf32(acc[im][in], afr[im], bfr[in]);
        }
        __syncthreads();
    }

    const int g = lid >> 2, cq = lid & 3;
#pragma unroll
    for (int im = 0; im < 2; im++) {
        const int mbase = bm + warp_m * 32 + im * 16 + g;
#pragma unroll
        for (int in = 0; in < 8; in++) {
            const int n0 = bn + warp_n * 64 + in * 8 + cq * 2;
            const float c0 = acc[im][in][0], c1 = acc[im][in][1];
            const float c2 = acc[im][in][2], c3 = acc[im][in][3];
            if (EPI == 0) {
                const float2 bv = *(const float2*)(bias + n0);
                const int h = n0 >> 6, d = n0 & 63;
#pragma unroll
                for (int rr = 0; rr < 2; rr++) {
                    const int m = mbase + rr * 8;
                    const int b = m >> 11, s = m & 2047;
                    float2 o; o.x = (rr ? c2 : c0) + bv.x; o.y = (rr ? c3 : c1) + bv.y;
                    *(float2*)&C[(((size_t)(b * NUM_HEADS + h) * SEQ) + s) * D_K + d] = o;
                }
            } else if (EPI == 1) {
                const float b0 = bias[n0], b1 = bias[n0 + 1];
                const int h = n0 >> 6, d = n0 & 63;
#pragma unroll
                for (int rr = 0; rr < 2; rr++) {
                    const int m = mbase + rr * 8;
                    const int b = m >> 11, s = m & 2047;
                    const size_t base = ((size_t)(b * NUM_HEADS + h) * D_K + d) * SEQ + s;
                    C[base]       = (rr ? c2 : c0) + b0;
                    C[base + SEQ] = (rr ? c3 : c1) + b1;
                }
            } else {
                const float2 bv = *(const float2*)(bias + n0);
#pragma unroll
                for (int rr = 0; rr < 2; rr++) {
                    const int m = mbase + rr * 8;
                    float2 o; o.x = (rr ? c2 : c0) + bv.x; o.y = (rr ? c3 : c1) + bv.y;
                    *(float2*)&C[(size_t)m * D_MODEL + n0] = o;
                }
            }
        }
    }
}

// ---------------------------------------------------------------------------
// flashA: per (m-tile 128, head) block — fused scores + exp + row-sum + ctx.
// No attention tensor traffic. Writes g_ctx and g_l.
// ---------------------------------------------------------------------------
#define FA_Q    0
#define FA_K0   (64 * ABLK)                  // 8448
#define FA_KB   (128 * BBLK)                 // 8448 per k-buffer (ka8 x na16)
#define FA_P    (FA_K0 + 2 * FA_KB)          // 25344
#define FA_V    (FA_P + 128 * ABLK)          // 42240 (ka16 x na8 of BBLK)
#define FA_PART (FA_V + 128 * BBLK)          // 50688
#define FA_LSUM (FA_PART + 256)              // 50944
#define FA_TOT  (FA_LSUM + 128)              // 51072 floats = 204288 B

__global__ void __launch_bounds__(256) flash_kernel()
{
    extern __shared__ float smf[];
    const int tid = threadIdx.x;
    const int wid = tid >> 5, lid = tid & 31;
    const int warp_m = wid >> 1, warp_n = wid & 1;
    const int g = lid >> 2, cq = lid & 3;
    const int bm = blockIdx.x * 128;
    const int bh = blockIdx.y;

    const float* qp = g_q + (size_t)bh * SEQ * D_K + (size_t)bm * D_K;
    const float* kp = g_k + (size_t)bh * SEQ * D_K;
    const float* vp = g_vt + (size_t)bh * D_K * SEQ;

    // ---- load Q tile into A-frag layout (rows 128 x k 64) ----
#pragma unroll
    for (int it = 0; it < 8; it++) {
        int f = tid + it * 256;
        int row = f >> 4, c4 = f & 15;
        float4 v = *(const float4*)(qp + (size_t)row * D_K + c4 * 4);
        int ma = row >> 4, r = row & 15;
        int ka = c4 >> 1;
        int slot = ((c4 & 1) << 1) | (r >> 3);
        float* p = smf + FA_Q + ((ka * 8 + ma) * ABLK + ((r & 7) << 4) + slot);
        p[0]  = __uint_as_float(rn_tf32(v.x));
        p[4]  = __uint_as_float(rn_tf32(v.y));
        p[8]  = __uint_as_float(rn_tf32(v.z));
        p[12] = __uint_as_float(rn_tf32(v.w));
    }

    float4 rk[8];
    auto ldg_k = [&](int t) {
        const float* kb = kp + (size_t)(t * 128) * D_K;
#pragma unroll
        for (int it = 0; it < 8; it++) {
            int f = tid + it * 256;
            int row = f >> 4, c4 = f & 15;
            rk[it] = *(const float4*)(kb + (size_t)row * D_K + c4 * 4);
        }
    };
    auto sts_k = [&](int buf) {
        float* db = smf + FA_K0 + buf * FA_KB;
#pragma unroll
        for (int it = 0; it < 8; it++) {
            int f = tid + it * 256;
            int row = f >> 4, c4 = f & 15;
            int na = row >> 3, nn = row & 7;
            int ka = c4 >> 1, slot = c4 & 1;
            float* p = db + ((ka * 16 + na) * BBLK + (nn << 3) + slot);
            p[0] = __uint_as_float(rn_tf32(rk[it].x));
            p[2] = __uint_as_float(rn_tf32(rk[it].y));
            p[4] = __uint_as_float(rn_tf32(rk[it].z));
            p[6] = __uint_as_float(rn_tf32(rk[it].w));
        }
    };

    // V chunk load/store (4 float4 per chunk; LDG issued before scatter half
    // so exp/scatter ALU covers the LDG latency)
    float4 rv[4];
    auto ldg_v = [&](int t, int half) {
        const float* vb = vp + t * 128;
#pragma unroll
        for (int it = 0; it < 4; it++) {
            int f = tid + (half * 4 + it) * 256;
            int row = f >> 5, c4 = f & 31;
            rv[it] = *(const float4*)(vb + (size_t)row * SEQ + c4 * 4);
        }
    };
    auto sts_v = [&](int half) {
#pragma unroll
        for (int it = 0; it < 4; it++) {
            int f = tid + (half * 4 + it) * 256;
            int row = f >> 5, c4 = f & 31;
            int na = row >> 3, nn = row & 7;
            int ka = c4 >> 1, slot = c4 & 1;
            float* p = smf + FA_V + ((ka * 8 + na) * BBLK + (nn << 3) + slot);
            p[0] = __uint_as_float(rn_tf32(rv[it].x));
            p[2] = __uint_as_float(rn_tf32(rv[it].y));
            p[4] = __uint_as_float(rn_tf32(rv[it].z));
            p[6] = __uint_as_float(rn_tf32(rv[it].w));
        }
    };

    // ctx accumulator: warp tile 32 rows x 32 d-cols
    float acc2[2][4][4];
#pragma unroll
    for (int im = 0; im < 2; im++)
#pragma unroll
        for (int in = 0; in < 4; in++)
#pragma unroll
            for (int c = 0; c < 4; c++) acc2[im][in][c] = 0.f;
    float racc[2][2] = {{0.f, 0.f}, {0.f, 0.f}};

    ldg_k(0); sts_k(0); ldg_k(1);
    __syncthreads();

    for (int t = 0; t < 16; t++) {
        if (t + 1 < 16) sts_k((t + 1) & 1);
        if (t + 2 < 16) ldg_k(t + 2);

        // ---- scores MMA: Q(128x64) x K_tile(128x64)^T ----
        float acc[2][8][4];
#pragma unroll
        for (int im = 0; im < 2; im++)
#pragma unroll
            for (int in = 0; in < 8; in++)
#pragma unroll
                for (int c = 0; c < 4; c++) acc[im][in][c] = 0.f;

        const float* Kd = smf + FA_K0 + (t & 1) * FA_KB;
#pragma unroll
        for (int ka = 0; ka < 8; ka++) {
            uint32_t afr[2][4];
#pragma unroll
            for (int im = 0; im < 2; im++) {
                const float4 v = *(const float4*)(smf + FA_Q + (ka * 8 + warp_m * 2 + im) * ABLK + lid * 4);
                afr[im][0] = __float_as_uint(v.x); afr[im][1] = __float_as_uint(v.y);
                afr[im][2] = __float_as_uint(v.z); afr[im][3] = __float_as_uint(v.w);
            }
            uint32_t bfr[8][2];
#pragma unroll
            for (int in = 0; in < 8; in++) {
                const float2 v = *(const float2*)(Kd + (ka * 16 + warp_n * 8 + in) * BBLK + lid * 2);
                bfr[in][0] = __float_as_uint(v.x); bfr[in][1] = __float_as_uint(v.y);
            }
#pragma unroll
            for (int im = 0; im < 2; im++)
#pragma unroll
                for (int in = 0; in < 8; in++)
                    mma_tf32(acc[im][in], afr[im], bfr[in]);
        }

        // ---- e = exp(s/8); row sums; float2 scatter to P-frag ----
        // Interleave V LDG chunks so scatter ALU covers LDG latency.
#pragma unroll
        for (int im = 0; im < 2; im++) {
            ldg_v(t, im);
            const int row_blk = warp_m * 2 + im;           // 16-row block idx
#pragma unroll
            for (int in = 0; in < 8; in++) {
                const int col0 = warp_n * 64 + in * 8 + cq * 2;
#pragma unroll
                for (int j2 = 0; j2 < 2; j2++) {
                    const int col = col0 + j2;
                    const float e0 = __expf(acc[im][in][j2] * 0.125f);
                    const float e1 = __expf(acc[im][in][2 + j2] * 0.125f);
                    racc[im][0] += e0;
                    racc[im][1] += e1;
                    const int kk = col & 7;
                    const int word = ((col >> 3) * 8 + row_blk) * ABLK +
                                     g * 16 + (kk & 3) * 4 + ((kk >> 2) << 1);
                    float2 o; o.x = __uint_as_float(rn_tf32(e0));
                    o.y = __uint_as_float(rn_tf32(e1));
                    *(float2*)(smf + FA_P + word) = o;
                }
            }
            sts_v(im);
        }
        __syncthreads();

        // ---- ctx MMA: P(128x128) x Vt(64x128)^T, warp tile 32r x 32d ----
#pragma unroll
        for (int ka = 0; ka < 16; ka++) {
            uint32_t afr[2][4];
#pragma unroll
            for (int im = 0; im < 2; im++) {
                const float4 v = *(const float4*)(smf + FA_P + (ka * 8 + warp_m * 2 + im) * ABLK + lid * 4);
                afr[im][0] = __float_as_uint(v.x); afr[im][1] = __float_as_uint(v.y);
                afr[im][2] = __float_as_uint(v.z); afr[im][3] = __float_as_uint(v.w);
            }
#pragma unroll
            for (int in = 0; in < 4; in++) {
                uint32_t bfr[2];
                const float2 v = *(const float2*)(smf + FA_V + (ka * 8 + warp_n * 4 + in) * BBLK + lid * 2);
                bfr[0] = __float_as_uint(v.x); bfr[1] = __float_as_uint(v.y);
#pragma unroll
                for (int im = 0; im < 2; im++)
                    mma_tf32(acc2[im][in], afr[im], bfr);
            }
        }
        __syncthreads();
    }

    // ---- finalize row sums (deterministic reduction) ----
#pragma unroll
    for (int im = 0; im < 2; im++)
#pragma unroll
        for (int rr = 0; rr < 2; rr++) {
            float s = racc[im][rr];
            s += __shfl_xor_sync(0xffffffffu, s, 1);
            s += __shfl_xor_sync(0xffffffffu, s, 2);
            if (cq == 0)
                smf[FA_PART + warp_n * 128 + warp_m * 32 + im * 16 + rr * 8 + g] = s;
        }
    __syncthreads();
    if (tid < 128) {
        float l = smf[FA_PART + tid] + smf[FA_PART + 128 + tid];
        smf[FA_LSUM + tid] = l;
        g_l[(size_t)bh * SEQ + bm + tid] = l;
    }
    __syncthreads();

    // ---- ctx epilogue: scale by 1/l, scatter to g_ctx ----
    const int b = bh >> 4, h = bh & 15;
#pragma unroll
    for (int im = 0; im < 2; im++) {
#pragma unroll
        for (int rr = 0; rr < 2; rr++) {
            const int rowl = warp_m * 32 + im * 16 + g + rr * 8;
            const float inv = 1.f / smf[FA_LSUM + rowl];
            const int srow = bm + rowl;
#pragma unroll
            for (int in = 0; in < 4; in++) {
                const int n0 = warp_n * 32 + in * 8 + cq * 2;
                float2 o;
                o.x = acc2[im][in][rr ? 2 : 0] * inv;
                o.y = acc2[im][in][rr ? 3 : 1] * inv;
                *(float2*)&g_ctx[((size_t)(b * SEQ + srow)) * D_MODEL + h * D_K + n0] = o;
            }
        }
    }
}

// ---------------------------------------------------------------------------
// attnW: recompute scores, write attn = exp(s/8) / l.  Write-once, streaming.
// ---------------------------------------------------------------------------
#define AW_Q   0
#define AW_K0  (64 * ABLK)
#define AW_INV (AW_K0 + 2 * FA_KB)
#define AW_TOT (AW_INV + 128)     // 25472 floats

__global__ void __launch_bounds__(256, 2) attnw_kernel(float* __restrict__ attn)
{
    extern __shared__ float smf[];
    const int tid = threadIdx.x;
    const int wid = tid >> 5, lid = tid & 31;
    const int warp_m = wid >> 1, warp_n = wid & 1;
    const int g = lid >> 2, cq = lid & 3;
    const int bm = blockIdx.x * 128;
    const int bh = blockIdx.y;

    const float* qp = g_q + (size_t)bh * SEQ * D_K + (size_t)bm * D_K;
    const float* kp = g_k + (size_t)bh * SEQ * D_K;
    float* ap = attn + (size_t)bh * SEQ * SEQ;

    if (tid < 128)
        smf[AW_INV + tid] = 1.f / g_l[(size_t)bh * SEQ + bm + tid];

#pragma unroll
    for (int it = 0; it < 8; it++) {
        int f = tid + it * 256;
        int row = f >> 4, c4 = f & 15;
        float4 v = *(const float4*)(qp + (size_t)row * D_K + c4 * 4);
        int ma = row >> 4, r = row & 15;
        int ka = c4 >> 1;
        int slot = ((c4 & 1) << 1) | (r >> 3);
        float* p = smf + AW_Q + ((ka * 8 + ma) * ABLK + ((r & 7) << 4) + slot);
        p[0]  = __uint_as_float(rn_tf32(v.x));
        p[4]  = __uint_as_float(rn_tf32(v.y));
        p[8]  = __uint_as_float(rn_tf32(v.z));
        p[12] = __uint_as_float(rn_tf32(v.w));
    }

    float4 rk[8];
    auto ldg_k = [&](int t) {
        const float* kb = kp + (size_t)(t * 128) * D_K;
#pragma unroll
        for (int it = 0; it < 8; it++) {
            int f = tid + it * 256;
            int row = f >> 4, c4 = f & 15;
            rk[it] = *(const float4*)(kb + (size_t)row * D_K + c4 * 4);
        }
    };
    auto sts_k = [&](int buf) {
        float* db = smf + AW_K0 + buf * FA_KB;
#pragma unroll
        for (int it = 0; it < 8; it++) {
            int f = tid + it * 256;
            int row = f >> 4, c4 = f & 15;
            int na = row >> 3, nn = row & 7;
            int ka = c4 >> 1, slot = c4 & 1;
            float* p = db + ((ka * 16 + na) * BBLK + (nn << 3) + slot);
            p[0] = __uint_as_float(rn_tf32(rk[it].x));
            p[2] = __uint_as_float(rn_tf32(rk[it].y));
            p[4] = __uint_as_float(rn_tf32(rk[it].z));
            p[6] = __uint_as_float(rn_tf32(rk[it].w));
        }
    };

    ldg_k(0); sts_k(0); ldg_k(1);
    __syncthreads();

    const int row0q = warp_m * 32 + g;
    const float inv0 = smf[AW_INV + row0q];
    const float inv8 = smf[AW_INV + row0q + 8];
    const float inv16 = smf[AW_INV + row0q + 16];
    const float inv24 = smf[AW_INV + row0q + 24];

    for (int t = 0; t < 16; t++) {
        if (t + 1 < 16) sts_k((t + 1) & 1);
        if (t + 2 < 16) ldg_k(t + 2);

        float acc[2][8][4];
#pragma unroll
        for (int im = 0; im < 2; im++)
#pragma unroll
            for (int in = 0; in < 8; in++)
#pragma unroll
                for (int c = 0; c < 4; c++) acc[im][in][c] = 0.f;

        const float* Kd = smf + AW_K0 + (t & 1) * FA_KB;
#pragma unroll
        for (int ka = 0; ka < 8; ka++) {
            uint32_t afr[2][4];
#pragma unroll
            for (int im = 0; im < 2; im++) {
                const float4 v = *(const float4*)(smf + AW_Q + (ka * 8 + warp_m * 2 + im) * ABLK + lid * 4);
                afr[im][0] = __float_as_uint(v.x); afr[im][1] = __float_as_uint(v.y);
                afr[im][2] = __float_as_uint(v.z); afr[im][3] = __float_as_uint(v.w);
            }
            uint32_t bfr[8][2];
#pragma unroll
            for (int in = 0; in < 8; in++) {
                const float2 v = *(const float2*)(Kd + (ka * 16 + warp_n * 8 + in) * BBLK + lid * 2);
                bfr[in][0] = __float_as_uint(v.x); bfr[in][1] = __float_as_uint(v.y);
            }
#pragma unroll
            for (int im = 0; im < 2; im++)
#pragma unroll
                for (int in = 0; in < 8; in++)
                    mma_tf32(acc[im][in], afr[im], bfr[in]);
        }

#pragma unroll
        for (int im = 0; im < 2; im++) {
            const int mrow = bm + warp_m * 32 + im * 16 + g;
            const float iv0 = im ? inv16 : inv0;
            const float iv1 = im ? inv24 : inv8;
#pragma unroll
            for (int in = 0; in < 8; in++) {
                const int n0 = t * 128 + warp_n * 64 + in * 8 + cq * 2;
                float2 o0, o1;
                o0.x = __expf(acc[im][in][0] * 0.125f) * iv0;
                o0.y = __expf(acc[im][in][1] * 0.125f) * iv0;
                o1.x = __expf(acc[im][in][2] * 0.125f) * iv1;
                o1.y = __expf(acc[im][in][3] * 0.125f) * iv1;
                __stcs((float2*)&ap[(size_t)mrow * SEQ + n0], o0);
                __stcs((float2*)&ap[(size_t)(mrow + 8) * SEQ + n0], o1);
            }
        }
        __syncthreads();
    }
}

extern "C" void kernel_launch(void* const* d_in, const int* in_sizes, int n_in,
                              void* d_out, int out_size) {
    const float* Q  = (const float*)d_in[0];
    const float* K  = (const float*)d_in[1];
    const float* V  = (const float*)d_in[2];
    const float* Wq = (const float*)d_in[3];
    const float* bq = (const float*)d_in[4];
    const float* Wk = (const float*)d_in[5];
    const float* bk = (const float*)d_in[6];
    const float* Wv = (const float*)d_in[7];
    const float* bv = (const float*)d_in[8];
    const float* Wo = (const float*)d_in[9];
    const float* bo = (const float*)d_in[10];

    float* out = (float*)d_out;

    const size_t OUT_ELEMS  = (size_t)M_ROWS * D_MODEL;
    const size_t ATTN_ELEMS = (size_t)BH * SEQ * SEQ;

    float* attn;
    if ((size_t)out_size >= OUT_ELEMS + ATTN_ELEMS) {
        attn = out + OUT_ELEMS;
    } else {
        void* p = nullptr;
        cudaGetSymbolAddress(&p, g_attn_fb);
        attn = (float*)p;
    }

    float *qp, *kp, *vtp, *cp;
    { void* t; cudaGetSymbolAddress(&t, g_q);   qp  = (float*)t; }
    { void* t; cudaGetSymbolAddress(&t, g_k);   kp  = (float*)t; }
    { void* t; cudaGetSymbolAddress(&t, g_vt);  vtp = (float*)t; }
    { void* t; cudaGetSymbolAddress(&t, g_ctx); cp  = (float*)t; }

    const int SMP  = (2 * 32 * ABLK + 2 * 64 * BBLK) * 4;  // proj smem bytes
    const int SMFA = FA_TOT * 4;
    const int SMAW = AW_TOT * 4;

    cudaFuncSetAttribute(mma_gemm<0>, cudaFuncAttributeMaxDynamicSharedMemorySize, SMP);
    cudaFuncSetAttribute(mma_gemm<1>, cudaFuncAttributeMaxDynamicSharedMemorySize, SMP);
    cudaFuncSetAttribute(mma_gemm<2>, cudaFuncAttributeMaxDynamicSharedMemorySize, SMP);
    cudaFuncSetAttribute(flash_kernel, cudaFuncAttributeMaxDynamicSharedMemorySize, SMFA);
    cudaFuncSetAttribute(attnw_kernel, cudaFuncAttributeMaxDynamicSharedMemorySize, SMAW);

    dim3 projGrid(D_MODEL / 128, M_ROWS / 128);     // (8, 64)
    mma_gemm<0><<<projGrid, 256, SMP>>>(Q, Wq, bq, qp, 1024, 1024, 1024);
    mma_gemm<0><<<projGrid, 256, SMP>>>(K, Wk, bk, kp, 1024, 1024, 1024);
    mma_gemm<1><<<projGrid, 256, SMP>>>(V, Wv, bv, vtp, 1024, 1024, 1024);

    dim3 attGrid(SEQ / 128, BH);                    // (16, 64)
    flash_kernel<<<attGrid, 256, SMFA>>>();
    attnw_kernel<<<attGrid, 256, SMAW>>>(attn);

    mma_gemm<2><<<projGrid, 256, SMP>>>(cp, Wo, bo, out, 1024, 1024, 1024);
}